// round 11
// baseline (speedup 1.0000x reference)
#include <cuda_runtime.h>
#include <cuda_fp16.h>
#include <math.h>
#include <stdint.h>

#define D 128
#define MAXN 50176   // 50000 padded up to multiple of 128
#define MAXE 602112

__device__ __half g_Q[MAXN * D];
__device__ __half g_K[MAXN * D];
__device__ __half g_V[MAXN * D];
__device__ float  g_agg[MAXN * D];
__device__ float  g_w[MAXE];

__device__ int g_cnt[MAXN];
__device__ int g_rowptr[MAXN + 1];
__device__ int g_cursor[MAXN];
__device__ int g_ssrc[MAXE];

// smem tile stride (floats), padded so ldmatrix rows hit disjoint banks
#define LDT 132
#define A_FLOATS (128 * LDT)
#define B64_FLOATS (64 * LDT)
#define QKV_SMEM ((A_FLOATS + B64_FLOATS) * 4)   // 101376 B -> 2 CTAs/SM
#define OPJ_SMEM (2 * A_FLOATS * 4)              // 135168 B

#define SIGSCALE 0.08838834764831845f    // 1/sqrt(128)

// ---------------------------------------------------------------------------
// helpers
// ---------------------------------------------------------------------------
__device__ __forceinline__ uint32_t f2tf32(float f) {
    uint32_t u;
    asm("cvt.rna.tf32.f32 %0, %1;" : "=r"(u) : "f"(f));
    return u;
}

__device__ __forceinline__ uint32_t smem_u32(const void* p) {
    uint32_t a;
    asm("{ .reg .u64 t; cvta.to.shared.u64 t, %1; cvt.u32.u64 %0, t; }" : "=r"(a) : "l"(p));
    return a;
}

__device__ __forceinline__ void ldsm_x4(uint32_t r[4], uint32_t saddr) {
    asm volatile("ldmatrix.sync.aligned.m8n8.x4.shared.b16 {%0,%1,%2,%3}, [%4];"
                 : "=r"(r[0]), "=r"(r[1]), "=r"(r[2]), "=r"(r[3]) : "r"(saddr));
}

__device__ __forceinline__ void mma_tf32(float d[4], const uint32_t a[4], const uint32_t b[2]) {
    asm volatile(
        "mma.sync.aligned.m16n8k8.row.col.f32.tf32.tf32.f32 "
        "{%0,%1,%2,%3}, {%4,%5,%6,%7}, {%8,%9}, {%0,%1,%2,%3};"
        : "+f"(d[0]), "+f"(d[1]), "+f"(d[2]), "+f"(d[3])
        : "r"(a[0]), "r"(a[1]), "r"(a[2]), "r"(a[3]), "r"(b[0]), "r"(b[1]));
}

// ---------------------------------------------------------------------------
// MMA main loop with ldmatrix fragment feeds (32x32 warp tile at (mb, nb)).
// ---------------------------------------------------------------------------
__device__ __forceinline__ void mma_loop_ldsm(uint32_t a_smem, uint32_t b_smem,
                                              int mb, int nb, int lane,
                                              float acc[2][4][4])
{
    const int lr8 = lane & 7;
    const int q   = lane >> 3;

    uint32_t a_base[2], b_base[2];
#pragma unroll
    for (int i = 0; i < 2; ++i)
        a_base[i] = a_smem + (uint32_t)(((mb + i * 16 + (q & 1) * 8 + lr8) * LDT
                                         + (q >> 1) * 4) * 4);
#pragma unroll
    for (int p = 0; p < 2; ++p)
        b_base[p] = b_smem + (uint32_t)(((nb + p * 16 + (q >> 1) * 8 + lr8) * LDT) * 4
                                        + (q & 1) * 16);

#pragma unroll
    for (int i = 0; i < 2; ++i)
#pragma unroll
        for (int j = 0; j < 4; ++j)
#pragma unroll
            for (int t = 0; t < 4; ++t) acc[i][j][t] = 0.0f;

#pragma unroll
    for (int k0 = 0; k0 < 16; ++k0) {
        const uint32_t koff = k0 * 32;
        uint32_t A0[4], A1[4], B0[4], B1[4];
        ldsm_x4(A0, a_base[0] + koff);
        ldsm_x4(A1, a_base[1] + koff);
        ldsm_x4(B0, b_base[0] + koff);
        ldsm_x4(B1, b_base[1] + koff);

        mma_tf32(acc[0][0], A0, &B0[0]);
        mma_tf32(acc[0][1], A0, &B0[2]);
        mma_tf32(acc[0][2], A0, &B1[0]);
        mma_tf32(acc[0][3], A0, &B1[2]);
        mma_tf32(acc[1][0], A1, &B0[0]);
        mma_tf32(acc[1][1], A1, &B0[2]);
        mma_tf32(acc[1][2], A1, &B1[0]);
        mma_tf32(acc[1][3], A1, &B1[2]);
    }
}

// ---------------------------------------------------------------------------
// QKV kernel, N-split: grid (mb, 6). fp16 output.
// ---------------------------------------------------------------------------
__global__ void __launch_bounds__(256, 2)
qkv_kernel(const float* __restrict__ X,
           const float* __restrict__ Wq, const float* __restrict__ Wk,
           const float* __restrict__ Wv,
           __half* __restrict__ Q, __half* __restrict__ K, __half* __restrict__ V,
           int N)
{
    extern __shared__ float smem[];
    uint32_t* Au = (uint32_t*)smem;
    uint32_t* Bu = (uint32_t*)(smem + A_FLOATS);

    const int tid = threadIdx.x;
    const int m0 = blockIdx.x * 128;
    const int wsel = blockIdx.y >> 1;
    const int c0 = (blockIdx.y & 1) * 64;
    const float* W = (wsel == 0) ? Wq : ((wsel == 1) ? Wk : Wv);
    __half*      O = (wsel == 0) ? Q  : ((wsel == 1) ? K  : V);

#pragma unroll
    for (int i = 0; i < 16; ++i) {
        int idx = tid + i * 256;
        int m = idx >> 5;
        int c = idx & 31;
        int gm = m0 + m;
        float4 f = (gm < N) ? *(const float4*)(X + (size_t)gm * D + c * 4)
                            : make_float4(0.f, 0.f, 0.f, 0.f);
        uint4 u = make_uint4(f2tf32(f.x), f2tf32(f.y), f2tf32(f.z), f2tf32(f.w));
        *(uint4*)(Au + m * LDT + c * 4) = u;
    }
#pragma unroll
    for (int i = 0; i < 8; ++i) {
        int idx = tid + i * 256;
        int r = idx >> 5;
        int c = idx & 31;
        float4 f = *(const float4*)(W + (size_t)(c0 + r) * D + c * 4);
        uint4 u = make_uint4(f2tf32(f.x), f2tf32(f.y), f2tf32(f.z), f2tf32(f.w));
        *(uint4*)(Bu + r * LDT + c * 4) = u;
    }
    __syncthreads();

    const int lane = tid & 31;
    const int warp = tid >> 5;
    const int mb = (warp & 3) * 32;
    const int nb = (warp >> 2) * 32;

    float acc[2][4][4];
    mma_loop_ldsm(smem_u32(Au), smem_u32(Bu), mb, nb, lane, acc);

    const int lq = lane >> 2;
    const int lr = lane & 3;
#pragma unroll
    for (int i = 0; i < 2; ++i) {
        int row = m0 + mb + i * 16 + lq;
#pragma unroll
        for (int j = 0; j < 4; ++j) {
            int col = c0 + nb + j * 8 + lr * 2;
            if (row < N)
                *(__half2*)(O + (size_t)row * D + col) =
                    __floats2half2_rn(acc[i][j][0], acc[i][j][1]);
            if (row + 8 < N)
                *(__half2*)(O + (size_t)(row + 8) * D + col) =
                    __floats2half2_rn(acc[i][j][2], acc[i][j][3]);
        }
    }
}

// ---------------------------------------------------------------------------
// O-proj + bias + residual + LayerNorm fused (full-width, 512 threads)
// ---------------------------------------------------------------------------
__global__ void __launch_bounds__(512, 1)
oproj_ln_kernel(const float* __restrict__ AGG, const float* __restrict__ Wo,
                const float* __restrict__ X,
                const float* __restrict__ bo, const float* __restrict__ gamma,
                const float* __restrict__ beta,
                float* __restrict__ out, int N)
{
    extern __shared__ float smem[];
    uint32_t* Au = (uint32_t*)smem;
    uint32_t* Bu = (uint32_t*)(smem + A_FLOATS);
    float* Hs = smem;
    __shared__ float P[384];

    const int tid = threadIdx.x;
    if (tid < 128)       P[tid]       = bo[tid];
    else if (tid < 256)  P[tid]       = gamma[tid - 128];
    else if (tid < 384)  P[tid]       = beta[tid - 256];

    const int m0 = blockIdx.x * 128;

#pragma unroll
    for (int i = 0; i < 8; ++i) {
        int idx = tid + i * 512;
        int m = idx >> 5;
        int c = idx & 31;
        int gm = m0 + m;
        float4 f = (gm < N) ? *(const float4*)(AGG + (size_t)gm * D + c * 4)
                            : make_float4(0.f, 0.f, 0.f, 0.f);
        uint4 u = make_uint4(f2tf32(f.x), f2tf32(f.y), f2tf32(f.z), f2tf32(f.w));
        *(uint4*)(Au + m * LDT + c * 4) = u;

        float4 g = *(const float4*)(Wo + (size_t)m * D + c * 4);
        uint4 ub = make_uint4(f2tf32(g.x), f2tf32(g.y), f2tf32(g.z), f2tf32(g.w));
        *(uint4*)(Bu + m * LDT + c * 4) = ub;
    }
    __syncthreads();

    const int lane = tid & 31;
    const int warp = tid >> 5;
    const int mb = (warp & 3) * 32;
    const int nb = (warp >> 2) * 32;

    float acc[2][4][4];
    mma_loop_ldsm(smem_u32(Au), smem_u32(Bu), mb, nb, lane, acc);
    __syncthreads();

    const int lq = lane >> 2;
    const int lr = lane & 3;

#pragma unroll
    for (int i = 0; i < 2; ++i) {
        int r = mb + i * 16 + lq;
#pragma unroll
        for (int j = 0; j < 4; ++j) {
            int c = nb + j * 8 + lr * 2;
            *(float2*)(Hs + r * LDT + c)       = make_float2(acc[i][j][0], acc[i][j][1]);
            *(float2*)(Hs + (r + 8) * LDT + c) = make_float2(acc[i][j][2], acc[i][j][3]);
        }
    }
    __syncthreads();

#pragma unroll
    for (int p = 0; p < 8; ++p) {
        int r = warp * 8 + p;
        int grow = m0 + r;
        if (grow >= N) continue;

        float4 h = *(float4*)(Hs + r * LDT + lane * 4);
        float4 xb = *(const float4*)(X + (size_t)grow * D + lane * 4);
        float4 bb = *(const float4*)(P + lane * 4);
        h.x += xb.x + bb.x; h.y += xb.y + bb.y;
        h.z += xb.z + bb.z; h.w += xb.w + bb.w;

        float s  = h.x + h.y + h.z + h.w;
        float s2 = h.x * h.x + h.y * h.y + h.z * h.z + h.w * h.w;
#pragma unroll
        for (int o = 16; o; o >>= 1) {
            s  += __shfl_xor_sync(0xffffffffu, s,  o);
            s2 += __shfl_xor_sync(0xffffffffu, s2, o);
        }
        float mu  = s * (1.0f / 128.0f);
        float var = s2 * (1.0f / 128.0f) - mu * mu;
        float rv  = rsqrtf(var + 1e-5f);

        float4 gm = *(const float4*)(P + 128 + lane * 4);
        float4 bt = *(const float4*)(P + 256 + lane * 4);
        float4 o;
        o.x = (h.x - mu) * rv * gm.x + bt.x;
        o.y = (h.y - mu) * rv * gm.y + bt.y;
        o.z = (h.z - mu) * rv * gm.z + bt.z;
        o.w = (h.w - mu) * rv * gm.w + bt.w;
        *(float4*)(out + (size_t)grow * D + lane * 4) = o;
    }
}

// ---------------------------------------------------------------------------
// CSR build: histogram -> scan -> scatter (1 edge per thread)
// ---------------------------------------------------------------------------
__global__ void zero_int_kernel(int* __restrict__ p, int n) {
    int i = blockIdx.x * blockDim.x + threadIdx.x;
    if (i < n) p[i] = 0;
}

__global__ void hist_kernel(const int* __restrict__ ei, int* __restrict__ cnt, int E) {
    int e = blockIdx.x * blockDim.x + threadIdx.x;
    if (e < E) atomicAdd(&cnt[ei[E + e]], 1);
}

__global__ void __launch_bounds__(1024, 1)
scan_kernel(const int* __restrict__ cnt, int* __restrict__ rowptr,
            int* __restrict__ cursor, int N)
{
    __shared__ int part[1024];
    const int t = threadIdx.x;
    const int chunk = (N + 1023) / 1024;
    const int b = t * chunk;
    const int e = min(b + chunk, N);

    int s = 0;
    for (int i = b; i < e; ++i) s += cnt[i];
    part[t] = s;
    __syncthreads();

    for (int o = 1; o < 1024; o <<= 1) {
        int v = (t >= o) ? part[t - o] : 0;
        __syncthreads();
        part[t] += v;
        __syncthreads();
    }

    int run = part[t] - s;
    for (int i = b; i < e; ++i) {
        rowptr[i] = run;
        cursor[i] = run;
        run += cnt[i];
    }
    if (t == 1023) rowptr[N] = part[1023];
}

__global__ void scatter_kernel(const int* __restrict__ ei, int* __restrict__ cursor,
                               int* __restrict__ ssrc, int E)
{
    int e = blockIdx.x * blockDim.x + threadIdx.x;
    if (e < E) {
        int dst = ei[E + e];
        int p = atomicAdd(&cursor[dst], 1);
        ssrc[p] = ei[e];
    }
}

// ---------------------------------------------------------------------------
// Logit kernel: warp per node; fp16 Q/K; working set Q+K = 77MB (L2-resident).
// w[slot] = sigmoid(dot(Q[node], K[ssrc[slot]]) / sqrt(D))
// ---------------------------------------------------------------------------
__global__ void __launch_bounds__(256)
logit_kernel(const int* __restrict__ ssrc,
             const int* __restrict__ rowptr,
             const __half* __restrict__ Q,
             const __half* __restrict__ K,
             float* __restrict__ w, int N)
{
    int node = (blockIdx.x * blockDim.x + threadIdx.x) >> 5;
    int lane = threadIdx.x & 31;
    if (node >= N) return;

    const int beg = rowptr[node];
    const int end = rowptr[node + 1];

    uint2 qu = *(const uint2*)(Q + (size_t)node * D + lane * 4);
    float2 q0 = __half22float2(*(const __half2*)&qu.x);
    float2 q1 = __half22float2(*(const __half2*)&qu.y);

    int e = beg;
    for (; e + 4 <= end; e += 4) {
        int s0 = ssrc[e], s1 = ssrc[e + 1], s2 = ssrc[e + 2], s3 = ssrc[e + 3];
        uint2 k0u = *(const uint2*)(K + (size_t)s0 * D + lane * 4);
        uint2 k1u = *(const uint2*)(K + (size_t)s1 * D + lane * 4);
        uint2 k2u = *(const uint2*)(K + (size_t)s2 * D + lane * 4);
        uint2 k3u = *(const uint2*)(K + (size_t)s3 * D + lane * 4);

        float2 a, b;
        float d0, d1, d2, d3;
        a = __half22float2(*(const __half2*)&k0u.x); b = __half22float2(*(const __half2*)&k0u.y);
        d0 = q0.x * a.x + q0.y * a.y + q1.x * b.x + q1.y * b.y;
        a = __half22float2(*(const __half2*)&k1u.x); b = __half22float2(*(const __half2*)&k1u.y);
        d1 = q0.x * a.x + q0.y * a.y + q1.x * b.x + q1.y * b.y;
        a = __half22float2(*(const __half2*)&k2u.x); b = __half22float2(*(const __half2*)&k2u.y);
        d2 = q0.x * a.x + q0.y * a.y + q1.x * b.x + q1.y * b.y;
        a = __half22float2(*(const __half2*)&k3u.x); b = __half22float2(*(const __half2*)&k3u.y);
        d3 = q0.x * a.x + q0.y * a.y + q1.x * b.x + q1.y * b.y;

#pragma unroll
        for (int o = 16; o; o >>= 1) {
            d0 += __shfl_xor_sync(0xffffffffu, d0, o);
            d1 += __shfl_xor_sync(0xffffffffu, d1, o);
            d2 += __shfl_xor_sync(0xffffffffu, d2, o);
            d3 += __shfl_xor_sync(0xffffffffu, d3, o);
        }
        if (lane == 0) {
            w[e]     = 1.0f / (1.0f + __expf(-d0 * SIGSCALE));
            w[e + 1] = 1.0f / (1.0f + __expf(-d1 * SIGSCALE));
            w[e + 2] = 1.0f / (1.0f + __expf(-d2 * SIGSCALE));
            w[e + 3] = 1.0f / (1.0f + __expf(-d3 * SIGSCALE));
        }
    }
    for (; e < end; ++e) {
        int s0 = ssrc[e];
        uint2 ku = *(const uint2*)(K + (size_t)s0 * D + lane * 4);
        float2 a = __half22float2(*(const __half2*)&ku.x);
        float2 b = __half22float2(*(const __half2*)&ku.y);
        float d0 = q0.x * a.x + q0.y * a.y + q1.x * b.x + q1.y * b.y;
#pragma unroll
        for (int o = 16; o; o >>= 1) d0 += __shfl_xor_sync(0xffffffffu, d0, o);
        if (lane == 0) w[e] = 1.0f / (1.0f + __expf(-d0 * SIGSCALE));
    }
}

// ---------------------------------------------------------------------------
// V-accumulate: warp per node; fp16 V; pure gather + FMA, no shuffles,
// no atomics, plain float4 store (also replaces zero_kernel).
// ---------------------------------------------------------------------------
__global__ void __launch_bounds__(256)
vacc_kernel(const int* __restrict__ ssrc,
            const int* __restrict__ rowptr,
            const float* __restrict__ wgt,
            const __half* __restrict__ V,
            float* __restrict__ agg, int N)
{
    int node = (blockIdx.x * blockDim.x + threadIdx.x) >> 5;
    int lane = threadIdx.x & 31;
    if (node >= N) return;

    const int beg = rowptr[node];
    const int end = rowptr[node + 1];

    float4 acc = make_float4(0.f, 0.f, 0.f, 0.f);

    int e = beg;
    for (; e + 8 <= end; e += 8) {
        int s0 = ssrc[e],     s1 = ssrc[e + 1], s2 = ssrc[e + 2], s3 = ssrc[e + 3];
        int s4 = ssrc[e + 4], s5 = ssrc[e + 5], s6 = ssrc[e + 6], s7 = ssrc[e + 7];
        float w0 = wgt[e],     w1 = wgt[e + 1], w2 = wgt[e + 2], w3 = wgt[e + 3];
        float w4 = wgt[e + 4], w5 = wgt[e + 5], w6 = wgt[e + 6], w7 = wgt[e + 7];
        uint2 u0 = *(const uint2*)(V + (size_t)s0 * D + lane * 4);
        uint2 u1 = *(const uint2*)(V + (size_t)s1 * D + lane * 4);
        uint2 u2 = *(const uint2*)(V + (size_t)s2 * D + lane * 4);
        uint2 u3 = *(const uint2*)(V + (size_t)s3 * D + lane * 4);
        uint2 u4 = *(const uint2*)(V + (size_t)s4 * D + lane * 4);
        uint2 u5 = *(const uint2*)(V + (size_t)s5 * D + lane * 4);
        uint2 u6 = *(const uint2*)(V + (size_t)s6 * D + lane * 4);
        uint2 u7 = *(const uint2*)(V + (size_t)s7 * D + lane * 4);

        float2 a, b;
#define ACC4(u, wv) \
        a = __half22float2(*(const __half2*)&(u).x); \
        b = __half22float2(*(const __half2*)&(u).y); \
        acc.x += (wv) * a.x; acc.y += (wv) * a.y; \
        acc.z += (wv) * b.x; acc.w += (wv) * b.y;
        ACC4(u0, w0) ACC4(u1, w1) ACC4(u2, w2) ACC4(u3, w3)
        ACC4(u4, w4) ACC4(u5, w5) ACC4(u6, w6) ACC4(u7, w7)
    }
    for (; e < end; ++e) {
        int s0 = ssrc[e];
        float w0 = wgt[e];
        uint2 u = *(const uint2*)(V + (size_t)s0 * D + lane * 4);
        float2 a, b;
        ACC4(u, w0)
    }
#undef ACC4

    *(float4*)(agg + (size_t)node * D + lane * 4) = acc;
}

// ---------------------------------------------------------------------------
// launch
// ---------------------------------------------------------------------------
extern "C" void kernel_launch(void* const* d_in, const int* in_sizes, int n_in,
                              void* d_out, int out_size)
{
    const float* x     = (const float*)d_in[0];
    const int*   ei    = (const int*)  d_in[1];
    const float* Wq    = (const float*)d_in[2];
    const float* Wk    = (const float*)d_in[3];
    const float* Wv    = (const float*)d_in[4];
    const float* Wo    = (const float*)d_in[5];
    const float* bo    = (const float*)d_in[6];
    const float* gamma = (const float*)d_in[7];
    const float* beta  = (const float*)d_in[8];
    float*       out   = (float*)d_out;

    const int N = in_sizes[0] / D;
    const int E = in_sizes[1] / 2;

    __half *Q, *K, *V;
    float *agg, *w;
    int *cnt, *rowptr, *cursor, *ssrc;
    cudaGetSymbolAddress((void**)&Q,      g_Q);
    cudaGetSymbolAddress((void**)&K,      g_K);
    cudaGetSymbolAddress((void**)&V,      g_V);
    cudaGetSymbolAddress((void**)&agg,    g_agg);
    cudaGetSymbolAddress((void**)&w,      g_w);
    cudaGetSymbolAddress((void**)&cnt,    g_cnt);
    cudaGetSymbolAddress((void**)&rowptr, g_rowptr);
    cudaGetSymbolAddress((void**)&cursor, g_cursor);
    cudaGetSymbolAddress((void**)&ssrc,   g_ssrc);

    cudaFuncSetAttribute(qkv_kernel, cudaFuncAttributeMaxDynamicSharedMemorySize, QKV_SMEM);
    cudaFuncSetAttribute(oproj_ln_kernel, cudaFuncAttributeMaxDynamicSharedMemorySize, OPJ_SMEM);

    const int mb = (N + 127) / 128;

    // CSR build
    zero_int_kernel<<<(N + 255) / 256, 256>>>(cnt, N);
    hist_kernel<<<(E + 255) / 256, 256>>>(ei, cnt, E);
    scan_kernel<<<1, 1024>>>(cnt, rowptr, cursor, N);
    scatter_kernel<<<(E + 255) / 256, 256>>>(ei, cursor, ssrc, E);

    // projections
    qkv_kernel<<<dim3(mb, 6), 256, QKV_SMEM>>>(x, Wq, Wk, Wv, Q, K, V, N);

    // edge phase: L2-resident fp16 gathers, no atomics
    logit_kernel<<<(N + 7) / 8, 256>>>(ssrc, rowptr, Q, K, w, N);
    vacc_kernel<<<(N + 7) / 8, 256>>>(ssrc, rowptr, w, V, agg, N);

    // output projection + LN
    oproj_ln_kernel<<<mb, 512, OPJ_SMEM>>>(agg, Wo, x, bo, gamma, beta, out, N);
}

// round 12
// speedup vs baseline: 1.3035x; 1.3035x over previous
#include <cuda_runtime.h>
#include <cuda_fp16.h>
#include <math.h>
#include <stdint.h>

#define D 128
#define MAXN 50176   // 50000 padded up to multiple of 128

__device__ __half g_Q[MAXN * D];
__device__ __half g_K[MAXN * D];
__device__ __half g_V[MAXN * D];
__device__ float  g_agg[MAXN * D];

// fp16 smem tile stride (halves): 136 -> row stride 272B = 16 mod 128,
// so 8 consecutive rows hit 8 distinct 16B bank groups (ldmatrix conflict-free)
#define LDH 136
#define A_HALFS (128 * LDH)
#define B64_HALFS (64 * LDH)
#define QKV_SMEM ((A_HALFS + B64_HALFS) * 2)   // 52224 B -> 4 CTAs/SM
// fp32 H-staging stride
#define LDT 132
#define OPJ_SMEM (2 * A_HALFS * 2)             // 69632 B (H fp32 67584 aliases it)

#define SIGSCALE 0.08838834764831845f    // 1/sqrt(128)

// ---------------------------------------------------------------------------
// helpers
// ---------------------------------------------------------------------------
__device__ __forceinline__ uint32_t smem_u32(const void* p) {
    uint32_t a;
    asm("{ .reg .u64 t; cvta.to.shared.u64 t, %1; cvt.u32.u64 %0, t; }" : "=r"(a) : "l"(p));
    return a;
}

__device__ __forceinline__ void ldsm_x4(uint32_t r[4], uint32_t saddr) {
    asm volatile("ldmatrix.sync.aligned.m8n8.x4.shared.b16 {%0,%1,%2,%3}, [%4];"
                 : "=r"(r[0]), "=r"(r[1]), "=r"(r[2]), "=r"(r[3]) : "r"(saddr));
}

__device__ __forceinline__ void mma_f16(float d[4], const uint32_t a[4], const uint32_t b[2]) {
    asm volatile(
        "mma.sync.aligned.m16n8k16.row.col.f32.f16.f16.f32 "
        "{%0,%1,%2,%3}, {%4,%5,%6,%7}, {%8,%9}, {%0,%1,%2,%3};"
        : "+f"(d[0]), "+f"(d[1]), "+f"(d[2]), "+f"(d[3])
        : "r"(a[0]), "r"(a[1]), "r"(a[2]), "r"(a[3]), "r"(b[0]), "r"(b[1]));
}

// ---------------------------------------------------------------------------
// fp16 MMA main loop, 32x32 warp tile at (mb, nb).
// A smem: [m][k] fp16 stride LDH; B smem: [n][k] fp16 stride LDH.
// Per k16 step: 2 A-LDSM.x4 + 2 B-LDSM.x4 + 8 HMMA. 8 steps total.
// ---------------------------------------------------------------------------
__device__ __forceinline__ void mma_loop_f16(uint32_t a_smem, uint32_t b_smem,
                                             int mb, int nb, int lane,
                                             float acc[2][4][4])
{
    const int lr8 = lane & 7;
    const int q   = lane >> 3;           // quadrant 0..3

    uint32_t a_base[2], b_base[2];
#pragma unroll
    for (int i = 0; i < 2; ++i)
        a_base[i] = a_smem + (uint32_t)(((mb + i * 16 + (q & 1) * 8 + lr8) * LDH) * 2
                                        + (q >> 1) * 16);
#pragma unroll
    for (int p = 0; p < 2; ++p)
        b_base[p] = b_smem + (uint32_t)(((nb + p * 16 + (q >> 1) * 8 + lr8) * LDH) * 2
                                        + (q & 1) * 16);

#pragma unroll
    for (int i = 0; i < 2; ++i)
#pragma unroll
        for (int j = 0; j < 4; ++j)
#pragma unroll
            for (int t = 0; t < 4; ++t) acc[i][j][t] = 0.0f;

#pragma unroll
    for (int k0 = 0; k0 < 8; ++k0) {
        const uint32_t koff = k0 * 32;   // 16 fp16 = 32 bytes per k-step
        uint32_t A0[4], A1[4], B0[4], B1[4];
        ldsm_x4(A0, a_base[0] + koff);
        ldsm_x4(A1, a_base[1] + koff);
        ldsm_x4(B0, b_base[0] + koff);
        ldsm_x4(B1, b_base[1] + koff);

        mma_f16(acc[0][0], A0, &B0[0]);
        mma_f16(acc[0][1], A0, &B0[2]);
        mma_f16(acc[0][2], A0, &B1[0]);
        mma_f16(acc[0][3], A0, &B1[2]);
        mma_f16(acc[1][0], A1, &B0[0]);
        mma_f16(acc[1][1], A1, &B0[2]);
        mma_f16(acc[1][2], A1, &B1[0]);
        mma_f16(acc[1][3], A1, &B1[2]);
    }
}

// convert a float4 to 4 halves packed in uint2
__device__ __forceinline__ uint2 f4_to_h4(float4 f) {
    __half2 h0 = __floats2half2_rn(f.x, f.y);
    __half2 h1 = __floats2half2_rn(f.z, f.w);
    uint2 u;
    u.x = *(uint32_t*)&h0;
    u.y = *(uint32_t*)&h1;
    return u;
}

// ---------------------------------------------------------------------------
// QKV kernel, N-split: grid (mb, 6). by>>1 selects weight, by&1 selects col half.
// CTA 256 threads, 128x64 tile, 52KB smem -> 4 CTAs/SM.
// ---------------------------------------------------------------------------
__global__ void __launch_bounds__(256, 4)
qkv_kernel(const float* __restrict__ X,
           const float* __restrict__ Wq, const float* __restrict__ Wk,
           const float* __restrict__ Wv,
           __half* __restrict__ Q, __half* __restrict__ K, __half* __restrict__ V,
           int N)
{
    extern __shared__ __half hsm[];
    __half* Ah = hsm;
    __half* Bh = hsm + A_HALFS;

    const int tid = threadIdx.x;
    const int m0 = blockIdx.x * 128;
    const int wsel = blockIdx.y >> 1;
    const int c0 = (blockIdx.y & 1) * 64;
    const float* W = (wsel == 0) ? Wq : ((wsel == 1) ? Wk : Wv);
    __half*      O = (wsel == 0) ? Q  : ((wsel == 1) ? K  : V);

    // A tile: 128 rows x 32 float4 -> fp16, 16 per thread
#pragma unroll
    for (int i = 0; i < 16; ++i) {
        int idx = tid + i * 256;
        int m = idx >> 5;
        int c = idx & 31;
        int gm = m0 + m;
        float4 f = (gm < N) ? *(const float4*)(X + (size_t)gm * D + c * 4)
                            : make_float4(0.f, 0.f, 0.f, 0.f);
        *(uint2*)(Ah + m * LDH + c * 4) = f4_to_h4(f);
    }
    // B tile: 64 rows (c0..c0+63 of W) x 32 float4 -> fp16, 8 per thread
#pragma unroll
    for (int i = 0; i < 8; ++i) {
        int idx = tid + i * 256;
        int r = idx >> 5;
        int c = idx & 31;
        float4 f = *(const float4*)(W + (size_t)(c0 + r) * D + c * 4);
        *(uint2*)(Bh + r * LDH + c * 4) = f4_to_h4(f);
    }
    __syncthreads();

    const int lane = tid & 31;
    const int warp = tid >> 5;
    const int mb = (warp & 3) * 32;
    const int nb = (warp >> 2) * 32;

    float acc[2][4][4];
    mma_loop_f16(smem_u32(Ah), smem_u32(Bh), mb, nb, lane, acc);

    const int lq = lane >> 2;
    const int lr = lane & 3;
#pragma unroll
    for (int i = 0; i < 2; ++i) {
        int row = m0 + mb + i * 16 + lq;
#pragma unroll
        for (int j = 0; j < 4; ++j) {
            int col = c0 + nb + j * 8 + lr * 2;
            if (row < N)
                *(__half2*)(O + (size_t)row * D + col) =
                    __floats2half2_rn(acc[i][j][0], acc[i][j][1]);
            if (row + 8 < N)
                *(__half2*)(O + (size_t)(row + 8) * D + col) =
                    __floats2half2_rn(acc[i][j][2], acc[i][j][3]);
        }
    }
}

// ---------------------------------------------------------------------------
// O-proj + bias + residual + LayerNorm fused (full-width, 512 threads)
// ---------------------------------------------------------------------------
__global__ void __launch_bounds__(512, 1)
oproj_ln_kernel(const float* __restrict__ AGG, const float* __restrict__ Wo,
                const float* __restrict__ X,
                const float* __restrict__ bo, const float* __restrict__ gamma,
                const float* __restrict__ beta,
                float* __restrict__ out, int N)
{
    extern __shared__ __half hsm[];
    __half* Ah = hsm;
    __half* Bh = hsm + A_HALFS;
    float* Hs = (float*)hsm;             // fp32 H staging aliases A/B after MMA
    __shared__ float P[384];

    const int tid = threadIdx.x;
    if (tid < 128)       P[tid]       = bo[tid];
    else if (tid < 256)  P[tid]       = gamma[tid - 128];
    else if (tid < 384)  P[tid]       = beta[tid - 256];

    const int m0 = blockIdx.x * 128;

    // A (agg) and B (Wo) tiles: 4096 float4 each, 8 per thread each
#pragma unroll
    for (int i = 0; i < 8; ++i) {
        int idx = tid + i * 512;
        int m = idx >> 5;
        int c = idx & 31;
        int gm = m0 + m;
        float4 f = (gm < N) ? *(const float4*)(AGG + (size_t)gm * D + c * 4)
                            : make_float4(0.f, 0.f, 0.f, 0.f);
        *(uint2*)(Ah + m * LDH + c * 4) = f4_to_h4(f);

        float4 g = *(const float4*)(Wo + (size_t)m * D + c * 4);
        *(uint2*)(Bh + m * LDH + c * 4) = f4_to_h4(g);
    }
    __syncthreads();

    const int lane = tid & 31;
    const int warp = tid >> 5;
    const int mb = (warp & 3) * 32;
    const int nb = (warp >> 2) * 32;

    float acc[2][4][4];
    mma_loop_f16(smem_u32(Ah), smem_u32(Bh), mb, nb, lane, acc);
    __syncthreads();   // everyone done reading fp16 tiles

    const int lq = lane >> 2;
    const int lr = lane & 3;

    // stage GEMM result tile into Hs (fp32, stride LDT, aliases Ah/Bh)
#pragma unroll
    for (int i = 0; i < 2; ++i) {
        int r = mb + i * 16 + lq;
#pragma unroll
        for (int j = 0; j < 4; ++j) {
            int c = nb + j * 8 + lr * 2;
            *(float2*)(Hs + r * LDT + c)       = make_float2(acc[i][j][0], acc[i][j][1]);
            *(float2*)(Hs + (r + 8) * LDT + c) = make_float2(acc[i][j][2], acc[i][j][3]);
        }
    }
    __syncthreads();

#pragma unroll
    for (int p = 0; p < 8; ++p) {
        int r = warp * 8 + p;
        int grow = m0 + r;
        if (grow >= N) continue;

        float4 h = *(float4*)(Hs + r * LDT + lane * 4);
        float4 xb = *(const float4*)(X + (size_t)grow * D + lane * 4);
        float4 bb = *(const float4*)(P + lane * 4);
        h.x += xb.x + bb.x; h.y += xb.y + bb.y;
        h.z += xb.z + bb.z; h.w += xb.w + bb.w;

        float s  = h.x + h.y + h.z + h.w;
        float s2 = h.x * h.x + h.y * h.y + h.z * h.z + h.w * h.w;
#pragma unroll
        for (int o = 16; o; o >>= 1) {
            s  += __shfl_xor_sync(0xffffffffu, s,  o);
            s2 += __shfl_xor_sync(0xffffffffu, s2, o);
        }
        float mu  = s * (1.0f / 128.0f);
        float var = s2 * (1.0f / 128.0f) - mu * mu;
        float rv  = rsqrtf(var + 1e-5f);

        float4 gm = *(const float4*)(P + 128 + lane * 4);
        float4 bt = *(const float4*)(P + 256 + lane * 4);
        float4 o;
        o.x = (h.x - mu) * rv * gm.x + bt.x;
        o.y = (h.y - mu) * rv * gm.y + bt.y;
        o.z = (h.z - mu) * rv * gm.z + bt.z;
        o.w = (h.w - mu) * rv * gm.w + bt.w;
        *(float4*)(out + (size_t)grow * D + lane * 4) = o;
    }
}

// ---------------------------------------------------------------------------
// zero kernel (float4)
// ---------------------------------------------------------------------------
__global__ void zero_kernel(float4* __restrict__ p, int n4) {
    int i = blockIdx.x * blockDim.x + threadIdx.x;
    if (i < n4) p[i] = make_float4(0.f, 0.f, 0.f, 0.f);
}

// ---------------------------------------------------------------------------
// Edge kernel (R10 form, REDG-floor optimal): one warp per edge, fp16 Q/K/V.
// logit = dot(Q[dst], K[src]) / sqrt(D); agg[dst] += sigmoid(logit) * V[src]
// ---------------------------------------------------------------------------
__global__ void edge_kernel(const int* __restrict__ ei,
                            const __half* __restrict__ Q,
                            const __half* __restrict__ K,
                            const __half* __restrict__ V,
                            float* __restrict__ agg,
                            int E)
{
    int warp = (blockIdx.x * blockDim.x + threadIdx.x) >> 5;
    int lane = threadIdx.x & 31;
    if (warp >= E) return;

    int src = ei[warp];       // edge_index[0][e]
    int dst = ei[E + warp];   // edge_index[1][e]

    uint2 qu = *(const uint2*)(Q + (size_t)dst * D + lane * 4);
    uint2 ku = *(const uint2*)(K + (size_t)src * D + lane * 4);
    float2 q0 = __half22float2(*(const __half2*)&qu.x);
    float2 q1 = __half22float2(*(const __half2*)&qu.y);
    float2 k0 = __half22float2(*(const __half2*)&ku.x);
    float2 k1 = __half22float2(*(const __half2*)&ku.y);

    float d = q0.x * k0.x + q0.y * k0.y + q1.x * k1.x + q1.y * k1.y;
#pragma unroll
    for (int o = 16; o; o >>= 1) d += __shfl_xor_sync(0xffffffffu, d, o);

    float s = 1.0f / (1.0f + __expf(-d * SIGSCALE));

    uint2 vu = *(const uint2*)(V + (size_t)src * D + lane * 4);
    float2 v0 = __half22float2(*(const __half2*)&vu.x);
    float2 v1 = __half22float2(*(const __half2*)&vu.y);
    float mx = s * v0.x, my = s * v0.y, mz = s * v1.x, mw = s * v1.y;

    float* p = &agg[(size_t)dst * D + lane * 4];
    asm volatile("red.global.add.v4.f32 [%0], {%1, %2, %3, %4};"
                 :: "l"(p), "f"(mx), "f"(my), "f"(mz), "f"(mw)
                 : "memory");
}

// ---------------------------------------------------------------------------
// launch
// ---------------------------------------------------------------------------
extern "C" void kernel_launch(void* const* d_in, const int* in_sizes, int n_in,
                              void* d_out, int out_size)
{
    const float* x     = (const float*)d_in[0];
    const int*   ei    = (const int*)  d_in[1];
    const float* Wq    = (const float*)d_in[2];
    const float* Wk    = (const float*)d_in[3];
    const float* Wv    = (const float*)d_in[4];
    const float* Wo    = (const float*)d_in[5];
    const float* bo    = (const float*)d_in[6];
    const float* gamma = (const float*)d_in[7];
    const float* beta  = (const float*)d_in[8];
    float*       out   = (float*)d_out;

    const int N = in_sizes[0] / D;
    const int E = in_sizes[1] / 2;

    __half *Q, *K, *V;
    float *agg;
    cudaGetSymbolAddress((void**)&Q,   g_Q);
    cudaGetSymbolAddress((void**)&K,   g_K);
    cudaGetSymbolAddress((void**)&V,   g_V);
    cudaGetSymbolAddress((void**)&agg, g_agg);

    cudaFuncSetAttribute(qkv_kernel, cudaFuncAttributeMaxDynamicSharedMemorySize, QKV_SMEM);
    cudaFuncSetAttribute(oproj_ln_kernel, cudaFuncAttributeMaxDynamicSharedMemorySize, OPJ_SMEM);

    const int mb = (N + 127) / 128;

    zero_kernel<<<(N * D / 4 + 255) / 256, 256>>>((float4*)agg, N * D / 4);

    qkv_kernel<<<dim3(mb, 6), 256, QKV_SMEM>>>(x, Wq, Wk, Wv, Q, K, V, N);

    edge_kernel<<<(E + 7) / 8, 256>>>(ei, Q, K, V, agg, E);

    oproj_ln_kernel<<<mb, 512, OPJ_SMEM>>>(agg, Wo, x, bo, gamma, beta, out, N);
}

// round 14
// speedup vs baseline: 1.3752x; 1.0550x over previous
#include <cuda_runtime.h>
#include <cuda_fp16.h>
#include <math.h>
#include <stdint.h>

#define D 128
#define MAXN 50176   // 50000 padded up to multiple of 128

__device__ __half g_Q[MAXN * D];
__device__ __half g_K[MAXN * D];
__device__ __half g_V[MAXN * D];
__device__ __half g_agg[MAXN * D];   // fp16 aggregation buffer

// fp16 smem tile stride (halves): 136 -> row stride 272B = 16 mod 128,
// so 8 consecutive rows hit 8 distinct 16B bank groups (ldmatrix conflict-free)
#define LDH 136
#define A_HALFS (128 * LDH)
#define B64_HALFS (64 * LDH)
#define QKV_SMEM ((A_HALFS + B64_HALFS) * 2)   // 52224 B -> 4 CTAs/SM
// fp32 H-staging stride
#define LDT 132
#define OPJ_SMEM (2 * A_HALFS * 2)             // 69632 B (H fp32 67584 aliases it)

#define SIGSCALE 0.08838834764831845f    // 1/sqrt(128)

// ---------------------------------------------------------------------------
// helpers
// ---------------------------------------------------------------------------
__device__ __forceinline__ uint32_t smem_u32(const void* p) {
    uint32_t a;
    asm("{ .reg .u64 t; cvta.to.shared.u64 t, %1; cvt.u32.u64 %0, t; }" : "=r"(a) : "l"(p));
    return a;
}

__device__ __forceinline__ void ldsm_x4(uint32_t r[4], uint32_t saddr) {
    asm volatile("ldmatrix.sync.aligned.m8n8.x4.shared.b16 {%0,%1,%2,%3}, [%4];"
                 : "=r"(r[0]), "=r"(r[1]), "=r"(r[2]), "=r"(r[3]) : "r"(saddr));
}

__device__ __forceinline__ void mma_f16(float d[4], const uint32_t a[4], const uint32_t b[2]) {
    asm volatile(
        "mma.sync.aligned.m16n8k16.row.col.f32.f16.f16.f32 "
        "{%0,%1,%2,%3}, {%4,%5,%6,%7}, {%8,%9}, {%0,%1,%2,%3};"
        : "+f"(d[0]), "+f"(d[1]), "+f"(d[2]), "+f"(d[3])
        : "r"(a[0]), "r"(a[1]), "r"(a[2]), "r"(a[3]), "r"(b[0]), "r"(b[1]));
}

// ---------------------------------------------------------------------------
// fp16 MMA main loop, 32x32 warp tile at (mb, nb).
// ---------------------------------------------------------------------------
__device__ __forceinline__ void mma_loop_f16(uint32_t a_smem, uint32_t b_smem,
                                             int mb, int nb, int lane,
                                             float acc[2][4][4])
{
    const int lr8 = lane & 7;
    const int q   = lane >> 3;

    uint32_t a_base[2], b_base[2];
#pragma unroll
    for (int i = 0; i < 2; ++i)
        a_base[i] = a_smem + (uint32_t)(((mb + i * 16 + (q & 1) * 8 + lr8) * LDH) * 2
                                        + (q >> 1) * 16);
#pragma unroll
    for (int p = 0; p < 2; ++p)
        b_base[p] = b_smem + (uint32_t)(((nb + p * 16 + (q >> 1) * 8 + lr8) * LDH) * 2
                                        + (q & 1) * 16);

#pragma unroll
    for (int i = 0; i < 2; ++i)
#pragma unroll
        for (int j = 0; j < 4; ++j)
#pragma unroll
            for (int t = 0; t < 4; ++t) acc[i][j][t] = 0.0f;

#pragma unroll
    for (int k0 = 0; k0 < 8; ++k0) {
        const uint32_t koff = k0 * 32;
        uint32_t A0[4], A1[4], B0[4], B1[4];
        ldsm_x4(A0, a_base[0] + koff);
        ldsm_x4(A1, a_base[1] + koff);
        ldsm_x4(B0, b_base[0] + koff);
        ldsm_x4(B1, b_base[1] + koff);

        mma_f16(acc[0][0], A0, &B0[0]);
        mma_f16(acc[0][1], A0, &B0[2]);
        mma_f16(acc[0][2], A0, &B1[0]);
        mma_f16(acc[0][3], A0, &B1[2]);
        mma_f16(acc[1][0], A1, &B0[0]);
        mma_f16(acc[1][1], A1, &B0[2]);
        mma_f16(acc[1][2], A1, &B1[0]);
        mma_f16(acc[1][3], A1, &B1[2]);
    }
}

__device__ __forceinline__ uint2 f4_to_h4(float4 f) {
    __half2 h0 = __floats2half2_rn(f.x, f.y);
    __half2 h1 = __floats2half2_rn(f.z, f.w);
    uint2 u;
    u.x = *(uint32_t*)&h0;
    u.y = *(uint32_t*)&h1;
    return u;
}

// ---------------------------------------------------------------------------
// QKV kernel, N-split: grid (mb, 6). CTA 256 threads, 128x64 tile, 4 CTAs/SM.
// ---------------------------------------------------------------------------
__global__ void __launch_bounds__(256, 4)
qkv_kernel(const float* __restrict__ X,
           const float* __restrict__ Wq, const float* __restrict__ Wk,
           const float* __restrict__ Wv,
           __half* __restrict__ Q, __half* __restrict__ K, __half* __restrict__ V,
           int N)
{
    extern __shared__ __half hsm[];
    __half* Ah = hsm;
    __half* Bh = hsm + A_HALFS;

    const int tid = threadIdx.x;
    const int m0 = blockIdx.x * 128;
    const int wsel = blockIdx.y >> 1;
    const int c0 = (blockIdx.y & 1) * 64;
    const float* W = (wsel == 0) ? Wq : ((wsel == 1) ? Wk : Wv);
    __half*      O = (wsel == 0) ? Q  : ((wsel == 1) ? K  : V);

#pragma unroll
    for (int i = 0; i < 16; ++i) {
        int idx = tid + i * 256;
        int m = idx >> 5;
        int c = idx & 31;
        int gm = m0 + m;
        float4 f = (gm < N) ? *(const float4*)(X + (size_t)gm * D + c * 4)
                            : make_float4(0.f, 0.f, 0.f, 0.f);
        *(uint2*)(Ah + m * LDH + c * 4) = f4_to_h4(f);
    }
#pragma unroll
    for (int i = 0; i < 8; ++i) {
        int idx = tid + i * 256;
        int r = idx >> 5;
        int c = idx & 31;
        float4 f = *(const float4*)(W + (size_t)(c0 + r) * D + c * 4);
        *(uint2*)(Bh + r * LDH + c * 4) = f4_to_h4(f);
    }
    __syncthreads();

    const int lane = tid & 31;
    const int warp = tid >> 5;
    const int mb = (warp & 3) * 32;
    const int nb = (warp >> 2) * 32;

    float acc[2][4][4];
    mma_loop_f16(smem_u32(Ah), smem_u32(Bh), mb, nb, lane, acc);

    const int lq = lane >> 2;
    const int lr = lane & 3;
#pragma unroll
    for (int i = 0; i < 2; ++i) {
        int row = m0 + mb + i * 16 + lq;
#pragma unroll
        for (int j = 0; j < 4; ++j) {
            int col = c0 + nb + j * 8 + lr * 2;
            if (row < N)
                *(__half2*)(O + (size_t)row * D + col) =
                    __floats2half2_rn(acc[i][j][0], acc[i][j][1]);
            if (row + 8 < N)
                *(__half2*)(O + (size_t)(row + 8) * D + col) =
                    __floats2half2_rn(acc[i][j][2], acc[i][j][3]);
        }
    }
}

// ---------------------------------------------------------------------------
// O-proj + bias + residual + LayerNorm fused (full-width, 512 threads).
// AGG is fp16: A-tile load is a straight copy (no cvt).
// ---------------------------------------------------------------------------
__global__ void __launch_bounds__(512, 1)
oproj_ln_kernel(const __half* __restrict__ AGG, const float* __restrict__ Wo,
                const float* __restrict__ X,
                const float* __restrict__ bo, const float* __restrict__ gamma,
                const float* __restrict__ beta,
                float* __restrict__ out, int N)
{
    extern __shared__ __half hsm[];
    __half* Ah = hsm;
    __half* Bh = hsm + A_HALFS;
    float* Hs = (float*)hsm;
    __shared__ float P[384];

    const int tid = threadIdx.x;
    if (tid < 128)       P[tid]       = bo[tid];
    else if (tid < 256)  P[tid]       = gamma[tid - 128];
    else if (tid < 384)  P[tid]       = beta[tid - 256];

    const int m0 = blockIdx.x * 128;

    // A tile: 128 rows x 16 uint4 (fp16 direct copy), 4 per thread
#pragma unroll
    for (int i = 0; i < 4; ++i) {
        int idx = tid + i * 512;          // 0..2047
        int m = idx >> 4;                 // row
        int c = idx & 15;                 // uint4 col (8 halves)
        int gm = m0 + m;
        uint4 v = (gm < N) ? *(const uint4*)(AGG + (size_t)gm * D + c * 8)
                           : make_uint4(0u, 0u, 0u, 0u);
        *(uint4*)(Ah + m * LDH + c * 8) = v;
    }
    // B tile: Wo fp32 -> fp16, 8 per thread
#pragma unroll
    for (int i = 0; i < 8; ++i) {
        int idx = tid + i * 512;
        int m = idx >> 5;
        int c = idx & 31;
        float4 g = *(const float4*)(Wo + (size_t)m * D + c * 4);
        *(uint2*)(Bh + m * LDH + c * 4) = f4_to_h4(g);
    }
    __syncthreads();

    const int lane = tid & 31;
    const int warp = tid >> 5;
    const int mb = (warp & 3) * 32;
    const int nb = (warp >> 2) * 32;

    float acc[2][4][4];
    mma_loop_f16(smem_u32(Ah), smem_u32(Bh), mb, nb, lane, acc);
    __syncthreads();

    const int lq = lane >> 2;
    const int lr = lane & 3;

#pragma unroll
    for (int i = 0; i < 2; ++i) {
        int r = mb + i * 16 + lq;
#pragma unroll
        for (int j = 0; j < 4; ++j) {
            int c = nb + j * 8 + lr * 2;
            *(float2*)(Hs + r * LDT + c)       = make_float2(acc[i][j][0], acc[i][j][1]);
            *(float2*)(Hs + (r + 8) * LDT + c) = make_float2(acc[i][j][2], acc[i][j][3]);
        }
    }
    __syncthreads();

#pragma unroll
    for (int p = 0; p < 8; ++p) {
        int r = warp * 8 + p;
        int grow = m0 + r;
        if (grow >= N) continue;

        float4 h = *(float4*)(Hs + r * LDT + lane * 4);
        float4 xb = *(const float4*)(X + (size_t)grow * D + lane * 4);
        float4 bb = *(const float4*)(P + lane * 4);
        h.x += xb.x + bb.x; h.y += xb.y + bb.y;
        h.z += xb.z + bb.z; h.w += xb.w + bb.w;

        float s  = h.x + h.y + h.z + h.w;
        float s2 = h.x * h.x + h.y * h.y + h.z * h.z + h.w * h.w;
#pragma unroll
        for (int o = 16; o; o >>= 1) {
            s  += __shfl_xor_sync(0xffffffffu, s,  o);
            s2 += __shfl_xor_sync(0xffffffffu, s2, o);
        }
        float mu  = s * (1.0f / 128.0f);
        float var = s2 * (1.0f / 128.0f) - mu * mu;
        float rv  = rsqrtf(var + 1e-5f);

        float4 gm = *(const float4*)(P + 128 + lane * 4);
        float4 bt = *(const float4*)(P + 256 + lane * 4);
        float4 o;
        o.x = (h.x - mu) * rv * gm.x + bt.x;
        o.y = (h.y - mu) * rv * gm.y + bt.y;
        o.z = (h.z - mu) * rv * gm.z + bt.z;
        o.w = (h.w - mu) * rv * gm.w + bt.w;
        *(float4*)(out + (size_t)grow * D + lane * 4) = o;
    }
}

// ---------------------------------------------------------------------------
// zero kernel (uint4 over fp16 agg)
// ---------------------------------------------------------------------------
__global__ void zero_kernel(uint4* __restrict__ p, int n16) {
    int i = blockIdx.x * blockDim.x + threadIdx.x;
    if (i < n16) p[i] = make_uint4(0u, 0u, 0u, 0u);
}

// ---------------------------------------------------------------------------
// Edge kernel: one warp per edge; fp16 gathers; fp16 vectorized reduction.
// All 32 lanes compute the dot; lanes 0..15 each handle 8 halves of the
// message via red.global.add.noftz.v4.f16x2 (16B per lane-op).
// ---------------------------------------------------------------------------
__global__ void edge_kernel(const int* __restrict__ ei,
                            const __half* __restrict__ Q,
                            const __half* __restrict__ K,
                            const __half* __restrict__ V,
                            __half* __restrict__ agg,
                            int E)
{
    int warp = (blockIdx.x * blockDim.x + threadIdx.x) >> 5;
    int lane = threadIdx.x & 31;
    if (warp >= E) return;

    int src = ei[warp];       // edge_index[0][e]
    int dst = ei[E + warp];   // edge_index[1][e]

    uint2 qu = *(const uint2*)(Q + (size_t)dst * D + lane * 4);
    uint2 ku = *(const uint2*)(K + (size_t)src * D + lane * 4);
    float2 q0 = __half22float2(*(const __half2*)&qu.x);
    float2 q1 = __half22float2(*(const __half2*)&qu.y);
    float2 k0 = __half22float2(*(const __half2*)&ku.x);
    float2 k1 = __half22float2(*(const __half2*)&ku.y);

    float d = q0.x * k0.x + q0.y * k0.y + q1.x * k1.x + q1.y * k1.y;
#pragma unroll
    for (int o = 16; o; o >>= 1) d += __shfl_xor_sync(0xffffffffu, d, o);

    float s = 1.0f / (1.0f + __expf(-d * SIGSCALE));

    if (lane < 16) {
        __half2 s2 = __float2half2_rn(s);
        uint4 a = *(const uint4*)(V + (size_t)src * D + lane * 8);

        __half2 m0 = __hmul2(*(__half2*)&a.x, s2);
        __half2 m1 = __hmul2(*(__half2*)&a.y, s2);
        __half2 m2 = __hmul2(*(__half2*)&a.z, s2);
        __half2 m3 = __hmul2(*(__half2*)&a.w, s2);

        __half* p = agg + (size_t)dst * D + lane * 8;
        asm volatile(
            "red.global.add.noftz.v4.f16x2 [%0], {%1, %2, %3, %4};"
            :: "l"(p),
               "r"(*(uint32_t*)&m0), "r"(*(uint32_t*)&m1),
               "r"(*(uint32_t*)&m2), "r"(*(uint32_t*)&m3)
            : "memory");
    }
}

// ---------------------------------------------------------------------------
// launch
// ---------------------------------------------------------------------------
extern "C" void kernel_launch(void* const* d_in, const int* in_sizes, int n_in,
                              void* d_out, int out_size)
{
    const float* x     = (const float*)d_in[0];
    const int*   ei    = (const int*)  d_in[1];
    const float* Wq    = (const float*)d_in[2];
    const float* Wk    = (const float*)d_in[3];
    const float* Wv    = (const float*)d_in[4];
    const float* Wo    = (const float*)d_in[5];
    const float* bo    = (const float*)d_in[6];
    const float* gamma = (const float*)d_in[7];
    const float* beta  = (const float*)d_in[8];
    float*       out   = (float*)d_out;

    const int N = in_sizes[0] / D;
    const int E = in_sizes[1] / 2;

    __half *Q, *K, *V, *agg;
    cudaGetSymbolAddress((void**)&Q,   g_Q);
    cudaGetSymbolAddress((void**)&K,   g_K);
    cudaGetSymbolAddress((void**)&V,   g_V);
    cudaGetSymbolAddress((void**)&agg, g_agg);

    cudaFuncSetAttribute(qkv_kernel, cudaFuncAttributeMaxDynamicSharedMemorySize, QKV_SMEM);
    cudaFuncSetAttribute(oproj_ln_kernel, cudaFuncAttributeMaxDynamicSharedMemorySize, OPJ_SMEM);

    const int mb = (N + 127) / 128;
    const int n16 = N * D / 8;   // uint4 count over fp16 agg

    zero_kernel<<<(n16 + 255) / 256, 256>>>((uint4*)agg, n16);

    qkv_kernel<<<dim3(mb, 6), 256, QKV_SMEM>>>(x, Wq, Wk, Wv, Q, K, V, N);

    edge_kernel<<<(E + 7) / 8, 256>>>(ei, Q, K, V, agg, E);

    oproj_ln_kernel<<<mb, 512, OPJ_SMEM>>>(agg, Wo, x, bo, gamma, beta, out, N);
}

// round 15
// speedup vs baseline: 1.8636x; 1.3551x over previous
#include <cuda_runtime.h>
#include <cuda_fp16.h>
#include <math.h>
#include <stdint.h>

#define D 128
#define MAXN 50176   // 50000 padded up to multiple of 128

__device__ __half g_Q[MAXN * D];
__device__ __half g_K[MAXN * D];
__device__ __half g_V[MAXN * D];
__device__ __half g_agg[MAXN * D];   // fp16 aggregation buffer

// fp16 smem tile stride (halves): 136 -> row stride 272B = 16 mod 128,
// so 8 consecutive rows hit 8 distinct 16B bank groups (ldmatrix conflict-free)
#define LDH 136
#define A_HALFS  (128 * LDH)
#define A64_HALFS (64 * LDH)
#define B64_HALFS (64 * LDH)
#define QKV_SMEM ((A_HALFS + B64_HALFS) * 2)    // 52224 B -> 4 CTAs/SM
#define OPJ_SMEM ((A64_HALFS + A_HALFS) * 2)    // 52224 B -> 4 CTAs/SM
// fp32 H-staging stride
#define LDT 132

#define SIGSCALE 0.08838834764831845f    // 1/sqrt(128)

// ---------------------------------------------------------------------------
// helpers
// ---------------------------------------------------------------------------
__device__ __forceinline__ uint32_t smem_u32(const void* p) {
    uint32_t a;
    asm("{ .reg .u64 t; cvta.to.shared.u64 t, %1; cvt.u32.u64 %0, t; }" : "=r"(a) : "l"(p));
    return a;
}

__device__ __forceinline__ void ldsm_x4(uint32_t r[4], uint32_t saddr) {
    asm volatile("ldmatrix.sync.aligned.m8n8.x4.shared.b16 {%0,%1,%2,%3}, [%4];"
                 : "=r"(r[0]), "=r"(r[1]), "=r"(r[2]), "=r"(r[3]) : "r"(saddr));
}

__device__ __forceinline__ void mma_f16(float d[4], const uint32_t a[4], const uint32_t b[2]) {
    asm volatile(
        "mma.sync.aligned.m16n8k16.row.col.f32.f16.f16.f32 "
        "{%0,%1,%2,%3}, {%4,%5,%6,%7}, {%8,%9}, {%0,%1,%2,%3};"
        : "+f"(d[0]), "+f"(d[1]), "+f"(d[2]), "+f"(d[3])
        : "r"(a[0]), "r"(a[1]), "r"(a[2]), "r"(a[3]), "r"(b[0]), "r"(b[1]));
}

// ---------------------------------------------------------------------------
// fp16 MMA main loop, 32x32 warp tile at (mb, nb).
// ---------------------------------------------------------------------------
__device__ __forceinline__ void mma_loop_f16(uint32_t a_smem, uint32_t b_smem,
                                             int mb, int nb, int lane,
                                             float acc[2][4][4])
{
    const int lr8 = lane & 7;
    const int q   = lane >> 3;

    uint32_t a_base[2], b_base[2];
#pragma unroll
    for (int i = 0; i < 2; ++i)
        a_base[i] = a_smem + (uint32_t)(((mb + i * 16 + (q & 1) * 8 + lr8) * LDH) * 2
                                        + (q >> 1) * 16);
#pragma unroll
    for (int p = 0; p < 2; ++p)
        b_base[p] = b_smem + (uint32_t)(((nb + p * 16 + (q >> 1) * 8 + lr8) * LDH) * 2
                                        + (q & 1) * 16);

#pragma unroll
    for (int i = 0; i < 2; ++i)
#pragma unroll
        for (int j = 0; j < 4; ++j)
#pragma unroll
            for (int t = 0; t < 4; ++t) acc[i][j][t] = 0.0f;

#pragma unroll
    for (int k0 = 0; k0 < 8; ++k0) {
        const uint32_t koff = k0 * 32;
        uint32_t A0[4], A1[4], B0[4], B1[4];
        ldsm_x4(A0, a_base[0] + koff);
        ldsm_x4(A1, a_base[1] + koff);
        ldsm_x4(B0, b_base[0] + koff);
        ldsm_x4(B1, b_base[1] + koff);

        mma_f16(acc[0][0], A0, &B0[0]);
        mma_f16(acc[0][1], A0, &B0[2]);
        mma_f16(acc[0][2], A0, &B1[0]);
        mma_f16(acc[0][3], A0, &B1[2]);
        mma_f16(acc[1][0], A1, &B0[0]);
        mma_f16(acc[1][1], A1, &B0[2]);
        mma_f16(acc[1][2], A1, &B1[0]);
        mma_f16(acc[1][3], A1, &B1[2]);
    }
}

__device__ __forceinline__ uint2 f4_to_h4(float4 f) {
    __half2 h0 = __floats2half2_rn(f.x, f.y);
    __half2 h1 = __floats2half2_rn(f.z, f.w);
    uint2 u;
    u.x = *(uint32_t*)&h0;
    u.y = *(uint32_t*)&h1;
    return u;
}

// ---------------------------------------------------------------------------
// QKV kernel, N-split: grid (mb, 6). CTA 256 threads, 128x64 tile, 4 CTAs/SM.
// ---------------------------------------------------------------------------
__global__ void __launch_bounds__(256, 4)
qkv_kernel(const float* __restrict__ X,
           const float* __restrict__ Wq, const float* __restrict__ Wk,
           const float* __restrict__ Wv,
           __half* __restrict__ Q, __half* __restrict__ K, __half* __restrict__ V,
           int N)
{
    extern __shared__ __half hsm[];
    __half* Ah = hsm;
    __half* Bh = hsm + A_HALFS;

    const int tid = threadIdx.x;
    const int m0 = blockIdx.x * 128;
    const int wsel = blockIdx.y >> 1;
    const int c0 = (blockIdx.y & 1) * 64;
    const float* W = (wsel == 0) ? Wq : ((wsel == 1) ? Wk : Wv);
    __half*      O = (wsel == 0) ? Q  : ((wsel == 1) ? K  : V);

#pragma unroll
    for (int i = 0; i < 16; ++i) {
        int idx = tid + i * 256;
        int m = idx >> 5;
        int c = idx & 31;
        int gm = m0 + m;
        float4 f = (gm < N) ? *(const float4*)(X + (size_t)gm * D + c * 4)
                            : make_float4(0.f, 0.f, 0.f, 0.f);
        *(uint2*)(Ah + m * LDH + c * 4) = f4_to_h4(f);
    }
#pragma unroll
    for (int i = 0; i < 8; ++i) {
        int idx = tid + i * 256;
        int r = idx >> 5;
        int c = idx & 31;
        float4 f = *(const float4*)(W + (size_t)(c0 + r) * D + c * 4);
        *(uint2*)(Bh + r * LDH + c * 4) = f4_to_h4(f);
    }
    __syncthreads();

    const int lane = tid & 31;
    const int warp = tid >> 5;
    const int mb = (warp & 3) * 32;
    const int nb = (warp >> 2) * 32;

    float acc[2][4][4];
    mma_loop_f16(smem_u32(Ah), smem_u32(Bh), mb, nb, lane, acc);

    const int lq = lane >> 2;
    const int lr = lane & 3;
#pragma unroll
    for (int i = 0; i < 2; ++i) {
        int row = m0 + mb + i * 16 + lq;
#pragma unroll
        for (int j = 0; j < 4; ++j) {
            int col = c0 + nb + j * 8 + lr * 2;
            if (row < N)
                *(__half2*)(O + (size_t)row * D + col) =
                    __floats2half2_rn(acc[i][j][0], acc[i][j][1]);
            if (row + 8 < N)
                *(__half2*)(O + (size_t)(row + 8) * D + col) =
                    __floats2half2_rn(acc[i][j][2], acc[i][j][3]);
        }
    }
}

// ---------------------------------------------------------------------------
// O-proj + bias + residual + LayerNorm fused. M-split: 64x128 tile per CTA,
// 256 threads, 52KB smem -> 4 CTAs/SM. LN keeps full 128-wide rows.
// ---------------------------------------------------------------------------
__global__ void __launch_bounds__(256, 4)
oproj_ln_kernel(const __half* __restrict__ AGG, const float* __restrict__ Wo,
                const float* __restrict__ X,
                const float* __restrict__ bo, const float* __restrict__ gamma,
                const float* __restrict__ beta,
                float* __restrict__ out, int N)
{
    extern __shared__ __half hsm[];
    __half* Ah = hsm;                    // 64 x LDH fp16
    __half* Bh = hsm + A64_HALFS;        // 128 x LDH fp16 (Wo)
    float* Hs = (float*)hsm;             // 64 x LDT fp32 staging (aliases)
    __shared__ float P[384];

    const int tid = threadIdx.x;
    if (tid < 128)      P[tid]       = bo[tid];
    else                P[tid]       = gamma[tid - 128];
    if (tid < 128)      P[256 + tid] = beta[tid];

    const int m0 = blockIdx.x * 64;

    // A tile: 64 rows x 16 uint4 (fp16 direct copy), 4 per thread
#pragma unroll
    for (int i = 0; i < 4; ++i) {
        int idx = tid + i * 256;          // 0..1023
        int m = idx >> 4;                 // row 0..63
        int c = idx & 15;                 // uint4 col
        int gm = m0 + m;
        uint4 v = (gm < N) ? *(const uint4*)(AGG + (size_t)gm * D + c * 8)
                           : make_uint4(0u, 0u, 0u, 0u);
        *(uint4*)(Ah + m * LDH + c * 8) = v;
    }
    // B tile: full Wo 128 rows fp32 -> fp16, 16 per thread
#pragma unroll
    for (int i = 0; i < 16; ++i) {
        int idx = tid + i * 256;          // 0..4095
        int m = idx >> 5;
        int c = idx & 31;
        float4 g = *(const float4*)(Wo + (size_t)m * D + c * 4);
        *(uint2*)(Bh + m * LDH + c * 4) = f4_to_h4(g);
    }
    __syncthreads();

    const int lane = tid & 31;
    const int warp = tid >> 5;
    const int mb = (warp & 1) * 32;      // 0 or 32 within 64-row tile
    const int nb = (warp >> 1) * 32;     // 0..96

    float acc[2][4][4];
    mma_loop_f16(smem_u32(Ah), smem_u32(Bh), mb, nb, lane, acc);
    __syncthreads();

    const int lq = lane >> 2;
    const int lr = lane & 3;

    // stage tile into Hs (fp32, stride LDT)
#pragma unroll
    for (int i = 0; i < 2; ++i) {
        int r = mb + i * 16 + lq;
#pragma unroll
        for (int j = 0; j < 4; ++j) {
            int c = nb + j * 8 + lr * 2;
            *(float2*)(Hs + r * LDT + c)       = make_float2(acc[i][j][0], acc[i][j][1]);
            *(float2*)(Hs + (r + 8) * LDT + c) = make_float2(acc[i][j][2], acc[i][j][3]);
        }
    }
    __syncthreads();

    // LN: 8 warps x 8 rows = 64 rows; lane covers cols 4l..4l+3
#pragma unroll
    for (int p = 0; p < 8; ++p) {
        int r = warp * 8 + p;
        int grow = m0 + r;
        if (grow >= N) continue;

        float4 h = *(float4*)(Hs + r * LDT + lane * 4);
        float4 xb = *(const float4*)(X + (size_t)grow * D + lane * 4);
        float4 bb = *(const float4*)(P + lane * 4);
        h.x += xb.x + bb.x; h.y += xb.y + bb.y;
        h.z += xb.z + bb.z; h.w += xb.w + bb.w;

        float s  = h.x + h.y + h.z + h.w;
        float s2 = h.x * h.x + h.y * h.y + h.z * h.z + h.w * h.w;
#pragma unroll
        for (int o = 16; o; o >>= 1) {
            s  += __shfl_xor_sync(0xffffffffu, s,  o);
            s2 += __shfl_xor_sync(0xffffffffu, s2, o);
        }
        float mu  = s * (1.0f / 128.0f);
        float var = s2 * (1.0f / 128.0f) - mu * mu;
        float rv  = rsqrtf(var + 1e-5f);

        float4 gm = *(const float4*)(P + 128 + lane * 4);
        float4 bt = *(const float4*)(P + 256 + lane * 4);
        float4 o;
        o.x = (h.x - mu) * rv * gm.x + bt.x;
        o.y = (h.y - mu) * rv * gm.y + bt.y;
        o.z = (h.z - mu) * rv * gm.z + bt.z;
        o.w = (h.w - mu) * rv * gm.w + bt.w;
        *(float4*)(out + (size_t)grow * D + lane * 4) = o;
    }
}

// ---------------------------------------------------------------------------
// zero kernel (uint4 over fp16 agg)
// ---------------------------------------------------------------------------
__global__ void zero_kernel(uint4* __restrict__ p, int n16) {
    int i = blockIdx.x * blockDim.x + threadIdx.x;
    if (i < n16) p[i] = make_uint4(0u, 0u, 0u, 0u);
}

// ---------------------------------------------------------------------------
// Edge kernel: TWO edges per warp, 16 lanes each. Full-warp utilization in
// every phase. Clamped index + predicated atomic keeps lanes converged.
// ---------------------------------------------------------------------------
__global__ void edge_kernel(const int* __restrict__ ei,
                            const __half* __restrict__ Q,
                            const __half* __restrict__ K,
                            const __half* __restrict__ V,
                            __half* __restrict__ agg,
                            int E)
{
    int gwarp = (blockIdx.x * blockDim.x + threadIdx.x) >> 5;
    int lane  = threadIdx.x & 31;
    int half  = lane >> 4;               // 0 or 1: which edge
    int l16   = lane & 15;

    int ew = gwarp * 2 + half;
    bool valid = (ew < E);
    int ewc = valid ? ew : (E - 1);

    int src = ei[ewc];        // edge_index[0][e]
    int dst = ei[E + ewc];    // edge_index[1][e]

    // Q[dst], K[src]: 16 lanes x 8 halves (16B) = full 256B row
    uint4 qu = *(const uint4*)(Q + (size_t)dst * D + l16 * 8);
    uint4 ku = *(const uint4*)(K + (size_t)src * D + l16 * 8);

    float d = 0.f;
#pragma unroll
    for (int t = 0; t < 4; ++t) {
        float2 qf = __half22float2(*((const __half2*)&qu + t));
        float2 kf = __half22float2(*((const __half2*)&ku + t));
        d += qf.x * kf.x + qf.y * kf.y;
    }
    // reduce within 16-lane half-warp
#pragma unroll
    for (int o = 8; o; o >>= 1) d += __shfl_xor_sync(0xffffffffu, d, o);

    float s = 1.0f / (1.0f + __expf(-d * SIGSCALE));
    __half2 s2 = __float2half2_rn(s);

    uint4 vu = *(const uint4*)(V + (size_t)src * D + l16 * 8);
    __half2 m0 = __hmul2(*(__half2*)&vu.x, s2);
    __half2 m1 = __hmul2(*(__half2*)&vu.y, s2);
    __half2 m2 = __hmul2(*(__half2*)&vu.z, s2);
    __half2 m3 = __hmul2(*(__half2*)&vu.w, s2);

    if (valid) {
        __half* p = agg + (size_t)dst * D + l16 * 8;
        asm volatile(
            "red.global.add.noftz.v4.f16x2 [%0], {%1, %2, %3, %4};"
            :: "l"(p),
               "r"(*(uint32_t*)&m0), "r"(*(uint32_t*)&m1),
               "r"(*(uint32_t*)&m2), "r"(*(uint32_t*)&m3)
            : "memory");
    }
}

// ---------------------------------------------------------------------------
// launch
// ---------------------------------------------------------------------------
extern "C" void kernel_launch(void* const* d_in, const int* in_sizes, int n_in,
                              void* d_out, int out_size)
{
    const float* x     = (const float*)d_in[0];
    const int*   ei    = (const int*)  d_in[1];
    const float* Wq    = (const float*)d_in[2];
    const float* Wk    = (const float*)d_in[3];
    const float* Wv    = (const float*)d_in[4];
    const float* Wo    = (const float*)d_in[5];
    const float* bo    = (const float*)d_in[6];
    const float* gamma = (const float*)d_in[7];
    const float* beta  = (const float*)d_in[8];
    float*       out   = (float*)d_out;

    const int N = in_sizes[0] / D;
    const int E = in_sizes[1] / 2;

    __half *Q, *K, *V, *agg;
    cudaGetSymbolAddress((void**)&Q,   g_Q);
    cudaGetSymbolAddress((void**)&K,   g_K);
    cudaGetSymbolAddress((void**)&V,   g_V);
    cudaGetSymbolAddress((void**)&agg, g_agg);

    cudaFuncSetAttribute(qkv_kernel, cudaFuncAttributeMaxDynamicSharedMemorySize, QKV_SMEM);
    cudaFuncSetAttribute(oproj_ln_kernel, cudaFuncAttributeMaxDynamicSharedMemorySize, OPJ_SMEM);

    const int mb = (N + 127) / 128;
    const int mb64 = (N + 63) / 64;
    const int n16 = N * D / 8;
    const int ewarps = (E + 1) / 2;

    zero_kernel<<<(n16 + 255) / 256, 256>>>((uint4*)agg, n16);

    qkv_kernel<<<dim3(mb, 6), 256, QKV_SMEM>>>(x, Wq, Wk, Wv, Q, K, V, N);

    edge_kernel<<<(ewarps + 7) / 8, 256>>>(ei, Q, K, V, agg, E);

    oproj_ln_kernel<<<mb64, 256, OPJ_SMEM>>>(agg, Wo, x, bo, gamma, beta, out, N);
}